// round 15
// baseline (speedup 1.0000x reference)
#include <cuda_runtime.h>

#define BT 96
#define CH 32              // bt per chunk (R8-proven optimum)
#define NCHUNK 3
#define Nn 512
#define Dd 64
#define NNb 16
#define MS 45

// ---------------- device scratch ----------------
__device__ float g_xq[BT*Nn*Dd];
__device__ float g_Q [BT*Nn*Dd];
__device__ float g_K [BT*Nn*Dd];
__device__ float g_V [BT*Nn*Dd];
__device__ float g_u [BT*Nn];
__device__ float g_M [BT*Nn];
__device__ float g_avo[BT*48*Dd];
__device__ int   g_cp[BT*Nn];

// ---------------- packed f32x2 helpers ----------------
__device__ __forceinline__ unsigned long long pk2(float lo, float hi) {
    unsigned long long r;
    asm("mov.b64 %0, {%1, %2};" : "=l"(r) : "f"(lo), "f"(hi));
    return r;
}
__device__ __forceinline__ void fma2(unsigned long long& a, unsigned long long x,
                                     unsigned long long w) {
    asm("fma.rn.f32x2 %0, %1, %2, %0;" : "+l"(a) : "l"(x), "l"(w));
}
__device__ __forceinline__ float2 up2(unsigned long long v) {
    float lo, hi;
    asm("mov.b64 {%0, %1}, %2;" : "=f"(lo), "=f"(hi) : "l"(v));
    float2 r; r.x = lo; r.y = hi; return r;
}

// ---------------- K1: x_ = x + ev ; Q,K,V GEMMs + u = V.Wp ----------------
// 256 threads, 32 rows/CTA, thread tile 2 rows x 4 cols
__global__ void __launch_bounds__(256) k_qkv(
    const float* __restrict__ x, const float* __restrict__ eigvec,
    const float* __restrict__ eigval,
    const float* __restrict__ Wq, const float* __restrict__ bq,
    const float* __restrict__ Wk, const float* __restrict__ bk,
    const float* __restrict__ Wv, const float* __restrict__ bv,
    const float* __restrict__ Wp, int bt0)
{
    __shared__ __align__(16) float xs[32*64];
    int bt = bt0 + (blockIdx.x >> 4);
    int nb = (blockIdx.x & 15) * 32;
    int tid = threadIdx.x;

    for (int idx = tid; idx < 2048; idx += 256) {
        int r = idx >> 6, d = idx & 63;
        int n = nb + r;
        float v = x[(bt*Nn + n)*Dd + d] + eigvec[d*Nn + n] * eigval[d];
        xs[idx] = v;
        g_xq[(bt*Nn + n)*Dd + d] = v;
    }
    __syncthreads();

    int rg = tid >> 4, j4 = tid & 15;
    const float4* wq4 = (const float4*)Wq;
    const float4* wk4 = (const float4*)Wk;
    const float4* wv4 = (const float4*)Wv;

    unsigned long long q01[2], q23[2], k01[2], k23[2], v01[2], v23[2];
    {
        float4 b = __ldg((const float4*)bq + j4);
        #pragma unroll
        for (int i = 0; i < 2; i++) { q01[i] = pk2(b.x, b.y); q23[i] = pk2(b.z, b.w); }
        b = __ldg((const float4*)bk + j4);
        #pragma unroll
        for (int i = 0; i < 2; i++) { k01[i] = pk2(b.x, b.y); k23[i] = pk2(b.z, b.w); }
        b = __ldg((const float4*)bv + j4);
        #pragma unroll
        for (int i = 0; i < 2; i++) { v01[i] = pk2(b.x, b.y); v23[i] = pk2(b.z, b.w); }
    }

    const float4* xp = (const float4*)xs;
    #pragma unroll
    for (int d4 = 0; d4 < 16; d4++) {
        float4 xr[2];
        xr[0] = xp[(rg*2+0)*16 + d4];
        xr[1] = xp[(rg*2+1)*16 + d4];
        #pragma unroll
        for (int kk = 0; kk < 4; kk++) {
            float4 wq = __ldg(wq4 + (d4*4+kk)*16 + j4);
            float4 wk = __ldg(wk4 + (d4*4+kk)*16 + j4);
            float4 wv = __ldg(wv4 + (d4*4+kk)*16 + j4);
            unsigned long long wq01 = pk2(wq.x, wq.y), wq23 = pk2(wq.z, wq.w);
            unsigned long long wk01 = pk2(wk.x, wk.y), wk23 = pk2(wk.z, wk.w);
            unsigned long long wv01 = pk2(wv.x, wv.y), wv23 = pk2(wv.z, wv.w);
            #pragma unroll
            for (int i = 0; i < 2; i++) {
                float xv = ((const float*)&xr[i])[kk];
                unsigned long long x2 = pk2(xv, xv);
                fma2(q01[i], x2, wq01); fma2(q23[i], x2, wq23);
                fma2(k01[i], x2, wk01); fma2(k23[i], x2, wk23);
                fma2(v01[i], x2, wv01); fma2(v23[i], x2, wv23);
            }
        }
    }

    float4 wp = __ldg((const float4*)Wp + j4);
    int nbase = (bt*Nn + nb + rg*2)*Dd;
    float up[2];
    #pragma unroll
    for (int i = 0; i < 2; i++) {
        float2 a = up2(q01[i]), b = up2(q23[i]);
        float4 o; o.x=a.x; o.y=a.y; o.z=b.x; o.w=b.y;
        ((float4*)(g_Q + nbase + i*Dd))[j4] = o;
        a = up2(k01[i]); b = up2(k23[i]);
        o.x=a.x; o.y=a.y; o.z=b.x; o.w=b.y;
        ((float4*)(g_K + nbase + i*Dd))[j4] = o;
        a = up2(v01[i]); b = up2(v23[i]);
        o.x=a.x; o.y=a.y; o.z=b.x; o.w=b.y;
        ((float4*)(g_V + nbase + i*Dd))[j4] = o;
        up[i] = o.x*wp.x + o.y*wp.y + o.z*wp.z + o.w*wp.w;
    }
    #pragma unroll
    for (int o = 8; o; o >>= 1) {
        #pragma unroll
        for (int i = 0; i < 2; i++)
            up[i] += __shfl_xor_sync(0xffffffffu, up[i], o);
    }
    if (j4 == 0) {
        g_u[bt*Nn + nb + rg*2    ] = up[0];
        g_u[bt*Nn + nb + rg*2 + 1] = up[1];
    }
}

// ---------------- K2: M[n] = Q[n] . sum_k u[j]K[j] + bp (warp per node) ----
__global__ void k_gat(const int* __restrict__ adj, const float* __restrict__ bp,
                      int bt0)
{
    int warp = threadIdx.x >> 5, lane = threadIdx.x & 31;
    int lg = blockIdx.x * 8 + warp;
    int bt = bt0 + (lg >> 9), n = lg & 511;
    int base = bt*Nn*Dd;
    float ax = 0.f, ay = 0.f;
    #pragma unroll
    for (int k = 0; k < NNb; k++) {
        int j = __ldg(adj + n*NNb + k);
        float uj = __ldg(g_u + bt*Nn + j);
        float2 kk = ((const float2*)(g_K + base + j*Dd))[lane];
        ax += uj*kk.x; ay += uj*kk.y;
    }
    float2 q = ((const float2*)(g_Q + base + n*Dd))[lane];
    float mm = q.x*ax + q.y*ay;
    #pragma unroll
    for (int o = 16; o; o >>= 1) mm += __shfl_xor_sync(0xffffffffu, mm, o);
    if (lane == 0) g_M[bt*Nn + n] = mm + __ldg(bp);
}

// ---------------- K3: topk + scores + softmax + cp + AV + avo ----------------
// dyn smem floats: sc[48*512] qs[48*64] ts[128*68] + ti[48] ints
__global__ void __launch_bounds__(1024) k_attn(const float* __restrict__ Wo,
                                               const float* __restrict__ bo,
                                               int bt0)
{
    extern __shared__ __align__(16) float sm[];
    float* sc = sm;                       // 24576
    float* qs = sm + 24576;               // 3072
    float* ts = qs + 3072;                // 8704 (128 rows, stride 68)
    int*   ti = (int*)(ts + 8704);        // 48

    int bt = bt0 + blockIdx.x, tid = threadIdx.x;   // 1024 threads
    int base = bt*Nn*Dd;

    // ---- preload K tile 0 into ts (latency hidden behind the sort) ----
    for (int idx = tid; idx < 2048; idx += 1024) {
        int r = idx >> 4, d4 = idx & 15;
        ((float4*)ts)[r*17 + d4] = ((const float4*)(g_K + base))[r*16 + d4];
    }

    // ---- top-45 hybrid bitonic (register keys; shfl j<32, smem j>=32) ----
    {
        unsigned long long* skey = (unsigned long long*)sc;
        unsigned long long key = 0;
        if (tid < 512) {
            float f = g_M[bt*Nn + tid];
            unsigned int u = __float_as_uint(f);
            u = (u & 0x80000000u) ? ~u : (u | 0x80000000u);
            key = ((unsigned long long)u << 32) | (unsigned)tid;
        }
        for (int k = 2; k <= 512; k <<= 1) {
            for (int j = k >> 1; j > 0; j >>= 1) {
                if (j >= 32) {
                    if (tid < 512) skey[tid] = key;
                    __syncthreads();
                    if (tid < 512) {
                        unsigned long long partner = skey[tid ^ j];
                        bool up = ((tid & k) == 0);
                        bool lower = ((tid & j) == 0);
                        unsigned long long mn = key < partner ? key : partner;
                        unsigned long long mx = key < partner ? partner : key;
                        key = (up == lower) ? mn : mx;
                    }
                    __syncthreads();
                } else {
                    if (tid < 512) {
                        unsigned long long partner =
                            __shfl_xor_sync(0xffffffffu, key, j);
                        bool up = ((tid & k) == 0);
                        bool lower = ((tid & j) == 0);
                        unsigned long long mn = key < partner ? key : partner;
                        unsigned long long mx = key < partner ? partner : key;
                        key = (up == lower) ? mn : mx;
                    }
                }
            }
        }
        if (tid >= 512 - MS && tid < 512)
            ti[511 - tid] = (int)(key & 0xffffffffu);
        __syncthreads();
    }

    // ---- gather Q_red (48 rows; 45..47 zero) ----
    for (int idx = tid; idx < 48*64; idx += 1024) {
        int m = idx >> 6, d = idx & 63;
        qs[idx] = (m < MS) ? g_Q[base + ti[m]*Dd + d] : 0.f;
    }

    const float4* qs4 = (const float4*)qs;
    int mi = tid >> 6, ri = tid & 63;

    // ---- scores: 4 tiles of 128 K-rows (tile 0 already resident) ----
    for (int t = 0; t < 4; t++) {
        __syncthreads();
        if (t > 0) {
            for (int idx = tid; idx < 2048; idx += 1024) {
                int r = idx >> 4, d4 = idx & 15;
                ((float4*)ts)[r*17 + d4] = ((const float4*)(g_K + base))[(t*128 + r)*16 + d4];
            }
            __syncthreads();
        }
        float s00=0,s01=0,s10=0,s11=0,s20=0,s21=0;
        const float4* tk = (const float4*)ts;
        #pragma unroll
        for (int d4 = 0; d4 < 16; d4++) {
            float4 q0 = qs4[(mi     )*16 + d4];
            float4 q1 = qs4[(mi + 16)*16 + d4];
            float4 q2 = qs4[(mi + 32)*16 + d4];
            float4 k0 = tk[ri*17 + d4];
            float4 k1 = tk[(ri+64)*17 + d4];
            s00 += q0.x*k0.x + q0.y*k0.y + q0.z*k0.z + q0.w*k0.w;
            s01 += q0.x*k1.x + q0.y*k1.y + q0.z*k1.z + q0.w*k1.w;
            s10 += q1.x*k0.x + q1.y*k0.y + q1.z*k0.z + q1.w*k0.w;
            s11 += q1.x*k1.x + q1.y*k1.y + q1.z*k1.z + q1.w*k1.w;
            s20 += q2.x*k0.x + q2.y*k0.y + q2.z*k0.z + q2.w*k0.w;
            s21 += q2.x*k1.x + q2.y*k1.y + q2.z*k1.z + q2.w*k1.w;
        }
        int nb = t*128;
        sc[(mi     )*512 + nb + ri     ] = s00*0.125f;
        sc[(mi     )*512 + nb + ri + 64] = s01*0.125f;
        sc[(mi + 16)*512 + nb + ri     ] = s10*0.125f;
        sc[(mi + 16)*512 + nb + ri + 64] = s11*0.125f;
        sc[(mi + 32)*512 + nb + ri     ] = s20*0.125f;
        sc[(mi + 32)*512 + nb + ri + 64] = s21*0.125f;
    }
    __syncthreads();

    // ---- preload V tile 0 into ts (dead region during softmax/cp) ----
    for (int idx = tid; idx < 2048; idx += 1024) {
        int r = idx >> 4, d4 = idx & 15;
        ((float4*)ts)[r*17 + d4] = ((const float4*)(g_V + base))[r*16 + d4];
    }

    // ---- softmax (warp per row) ----
    {
        int warp = tid >> 5, lane = tid & 31;
        for (int m = warp; m < MS; m += 32) {
            float* row = sc + m*512;
            float rv[16];
            float mx = -1e30f;
            #pragma unroll
            for (int k = 0; k < 16; k++) { rv[k] = row[lane + 32*k]; mx = fmaxf(mx, rv[k]); }
            #pragma unroll
            for (int o = 16; o; o >>= 1) mx = fmaxf(mx, __shfl_xor_sync(0xffffffffu, mx, o));
            float s = 0.f;
            #pragma unroll
            for (int k = 0; k < 16; k++) { rv[k] = __expf(rv[k] - mx); s += rv[k]; }
            #pragma unroll
            for (int o = 16; o; o >>= 1) s += __shfl_xor_sync(0xffffffffu, s, o);
            float rinv = 1.f / s;
            #pragma unroll
            for (int k = 0; k < 16; k++) row[lane + 32*k] = rv[k]*rinv;
        }
        for (int idx = tid; idx < 3*512; idx += 1024) sc[MS*512 + idx] = 0.f;
    }
    __syncthreads();

    // ---- cp = argmax_m attn[:,n] (first-max ties) ----
    if (tid < 512) {
        int n = tid;
        float bv = sc[n]; int bi = 0;
        for (int m = 1; m < MS; m++) {
            float v = sc[m*512 + n];
            if (v > bv) { bv = v; bi = m; }
        }
        g_cp[bt*Nn + n] = bi;
    }

    // ---- av = attn @ V (tile 0 already resident) ----
    int di = ri;
    float a0 = 0.f, a1 = 0.f, a2 = 0.f;
    for (int t = 0; t < 4; t++) {
        __syncthreads();
        if (t > 0) {
            for (int idx = tid; idx < 2048; idx += 1024) {
                int r = idx >> 4, d4 = idx & 15;
                ((float4*)ts)[r*17 + d4] = ((const float4*)(g_V + base))[(t*128 + r)*16 + d4];
            }
            __syncthreads();
        }
        const float4* p0 = (const float4*)(sc + (mi     )*512 + t*128);
        const float4* p1 = (const float4*)(sc + (mi + 16)*512 + t*128);
        const float4* p2 = (const float4*)(sc + (mi + 32)*512 + t*128);
        #pragma unroll
        for (int r4 = 0; r4 < 32; r4++) {
            float4 w0 = p0[r4], w1 = p1[r4], w2 = p2[r4];
            float v;
            v = ts[(r4*4+0)*68 + di]; a0 += w0.x*v; a1 += w1.x*v; a2 += w2.x*v;
            v = ts[(r4*4+1)*68 + di]; a0 += w0.y*v; a1 += w1.y*v; a2 += w2.y*v;
            v = ts[(r4*4+2)*68 + di]; a0 += w0.z*v; a1 += w1.z*v; a2 += w2.z*v;
            v = ts[(r4*4+3)*68 + di]; a0 += w0.w*v; a1 += w1.w*v; a2 += w2.w*v;
        }
    }
    __syncthreads();
    qs[(mi     )*64 + di] = a0;
    qs[(mi + 16)*64 + di] = a1;
    qs[(mi + 32)*64 + di] = a2;
    __syncthreads();

    // ---- avo = av @ Wo + bo ----
    {
        float b = __ldg(bo + di);
        float c0 = b, c1 = b, c2 = b;
        #pragma unroll
        for (int d4 = 0; d4 < 16; d4++) {
            float4 q0 = qs4[(mi     )*16 + d4];
            float4 q1 = qs4[(mi + 16)*16 + d4];
            float4 q2 = qs4[(mi + 32)*16 + d4];
            float w0 = __ldg(Wo + (d4*4+0)*64 + di);
            float w1 = __ldg(Wo + (d4*4+1)*64 + di);
            float w2 = __ldg(Wo + (d4*4+2)*64 + di);
            float w3 = __ldg(Wo + (d4*4+3)*64 + di);
            c0 += q0.x*w0 + q0.y*w1 + q0.z*w2 + q0.w*w3;
            c1 += q1.x*w0 + q1.y*w1 + q1.z*w2 + q1.w*w3;
            c2 += q2.x*w0 + q2.y*w1 + q2.z*w2 + q2.w*w3;
        }
        g_avo[(bt*48 + mi     )*64 + di] = c0;
        g_avo[(bt*48 + mi + 16)*64 + di] = c1;
        g_avo[(bt*48 + mi + 32)*64 + di] = c2;
    }
}

// ---------------- K4: gather + LN + FFN + LN -> out ------------------------
// 256 threads, 32 rows/CTA, thread tile 2 rows x 4 cols
__global__ void __launch_bounds__(256) k_out(
    const float* __restrict__ W1, const float* __restrict__ b1,
    const float* __restrict__ W2, const float* __restrict__ b2,
    float* __restrict__ out, int bt0)
{
    extern __shared__ __align__(16) float sm[];
    float* vs = sm;          // 32 rows, stride 68 = 2176
    float* hs = sm + 2176;

    int tid = threadIdx.x;   // 256
    int bt = bt0 + (blockIdx.x >> 4);
    int n0 = (blockIdx.x & 15) * 32;

    // gather avo[cp] + residual
    for (int idx = tid; idx < 512; idx += 256) {
        int r = idx >> 4, d4 = idx & 15;
        int c = g_cp[bt*Nn + n0 + r];
        float4 a = ((const float4*)(g_avo + (bt*48 + c)*Dd))[d4];
        float4 b = ((const float4*)(g_xq + (bt*Nn + n0 + r)*Dd))[d4];
        a.x += b.x; a.y += b.y; a.z += b.z; a.w += b.w;
        ((float4*)vs)[r*17 + d4] = a;
    }
    __syncthreads();

    // LN rows of vs
    {
        int warp = tid >> 5, lane = tid & 31;
        for (int r = warp; r < 32; r += 8) {
            float a = vs[r*68 + lane], b = vs[r*68 + lane + 32];
            float s = a + b;
            #pragma unroll
            for (int o = 16; o; o >>= 1) s += __shfl_xor_sync(0xffffffffu, s, o);
            float mu = s * (1.f/64.f);
            float da = a - mu, db = b - mu;
            float v2 = da*da + db*db;
            #pragma unroll
            for (int o = 16; o; o >>= 1) v2 += __shfl_xor_sync(0xffffffffu, v2, o);
            float rr = rsqrtf(v2*(1.f/64.f) + 1e-5f);
            vs[r*68 + lane] = da*rr; vs[r*68 + lane + 32] = db*rr;
        }
    }
    __syncthreads();

    int rg = tid >> 4, j4 = tid & 15;   // rg 0..15 -> rows rg*2, rg*2+1
    const float4* w14 = (const float4*)W1;
    const float4* w24 = (const float4*)W2;
    float4 acc[2];

    // GEMM: hs = relu(vs@W1 + b1)
    {
        float4 b4 = __ldg((const float4*)b1 + j4);
        acc[0] = b4; acc[1] = b4;
        const float4* xp = (const float4*)vs;
        #pragma unroll
        for (int d4 = 0; d4 < 16; d4++) {
            float4 xr[2];
            xr[0] = xp[(rg*2+0)*17 + d4];
            xr[1] = xp[(rg*2+1)*17 + d4];
            #pragma unroll
            for (int kk = 0; kk < 4; kk++) {
                float4 w = __ldg(w14 + (d4*4+kk)*16 + j4);
                #pragma unroll
                for (int i = 0; i < 2; i++) {
                    float xv = ((const float*)&xr[i])[kk];
                    acc[i].x += xv*w.x; acc[i].y += xv*w.y; acc[i].z += xv*w.z; acc[i].w += xv*w.w;
                }
            }
        }
        #pragma unroll
        for (int i = 0; i < 2; i++) {
            acc[i].x = fmaxf(acc[i].x, 0.f); acc[i].y = fmaxf(acc[i].y, 0.f);
            acc[i].z = fmaxf(acc[i].z, 0.f); acc[i].w = fmaxf(acc[i].w, 0.f);
            ((float4*)hs)[(rg*2+i)*17 + j4] = acc[i];
        }
    }
    __syncthreads();

    // GEMM: o = hs@W2 + b2 + vs -> vs
    {
        float4 b4 = __ldg((const float4*)b2 + j4);
        acc[0] = b4; acc[1] = b4;
        const float4* xp = (const float4*)hs;
        #pragma unroll
        for (int d4 = 0; d4 < 16; d4++) {
            float4 xr[2];
            xr[0] = xp[(rg*2+0)*17 + d4];
            xr[1] = xp[(rg*2+1)*17 + d4];
            #pragma unroll
            for (int kk = 0; kk < 4; kk++) {
                float4 w = __ldg(w24 + (d4*4+kk)*16 + j4);
                #pragma unroll
                for (int i = 0; i < 2; i++) {
                    float xv = ((const float*)&xr[i])[kk];
                    acc[i].x += xv*w.x; acc[i].y += xv*w.y; acc[i].z += xv*w.z; acc[i].w += xv*w.w;
                }
            }
        }
        #pragma unroll
        for (int i = 0; i < 2; i++) {
            float4 vv = ((const float4*)vs)[(rg*2+i)*17 + j4];
            acc[i].x += vv.x; acc[i].y += vv.y; acc[i].z += vv.z; acc[i].w += vv.w;
        }
        __syncthreads();
        #pragma unroll
        for (int i = 0; i < 2; i++)
            ((float4*)vs)[(rg*2+i)*17 + j4] = acc[i];
    }
    __syncthreads();

    // final LN -> out
    {
        int warp = tid >> 5, lane = tid & 31;
        for (int r = warp; r < 32; r += 8) {
            float a = vs[r*68 + lane], b = vs[r*68 + lane + 32];
            float s = a + b;
            #pragma unroll
            for (int o = 16; o; o >>= 1) s += __shfl_xor_sync(0xffffffffu, s, o);
            float mu = s * (1.f/64.f);
            float da = a - mu, db = b - mu;
            float v2 = da*da + db*db;
            #pragma unroll
            for (int o = 16; o; o >>= 1) v2 += __shfl_xor_sync(0xffffffffu, v2, o);
            float rr = rsqrtf(v2*(1.f/64.f) + 1e-5f);
            float* po = out + (bt*Nn + n0 + r)*Dd;
            po[lane] = da*rr; po[lane + 32] = db*rr;
        }
    }
}

// ---------------- launch: 3-chunk pipelined streams (R8 config) -------------
extern "C" void kernel_launch(void* const* d_in, const int* in_sizes, int n_in,
                              void* d_out, int out_size)
{
    const float* x      = (const float*)d_in[0];
    const int*   adj    = (const int*)  d_in[1];
    const float* eigvec = (const float*)d_in[2];
    const float* eigval = (const float*)d_in[3];
    const float* Wq = (const float*)d_in[4];  const float* bq = (const float*)d_in[5];
    const float* Wk = (const float*)d_in[6];  const float* bk = (const float*)d_in[7];
    const float* Wv = (const float*)d_in[8];  const float* bv = (const float*)d_in[9];
    const float* Wo = (const float*)d_in[10]; const float* bo = (const float*)d_in[11];
    const float* Wp = (const float*)d_in[12]; const float* bp = (const float*)d_in[13];
    const float* W1 = (const float*)d_in[14]; const float* b1 = (const float*)d_in[15];
    const float* W2 = (const float*)d_in[16]; const float* b2 = (const float*)d_in[17];
    float* out = (float*)d_out;

    static cudaStream_t s1 = 0, s2 = 0;
    static cudaEvent_t ef = 0, e1 = 0, e2 = 0;
    static int inited = 0;
    if (!inited) {
        cudaStreamCreateWithFlags(&s1, cudaStreamNonBlocking);
        cudaStreamCreateWithFlags(&s2, cudaStreamNonBlocking);
        cudaEventCreateWithFlags(&ef, cudaEventDisableTiming);
        cudaEventCreateWithFlags(&e1, cudaEventDisableTiming);
        cudaEventCreateWithFlags(&e2, cudaEventDisableTiming);
        cudaFuncSetAttribute(k_attn, cudaFuncAttributeMaxDynamicSharedMemorySize, 145600);
        cudaFuncSetAttribute(k_out,  cudaFuncAttributeMaxDynamicSharedMemorySize, 17408);
        inited = 1;
    }

    // fork
    cudaEventRecord(ef, 0);
    cudaStreamWaitEvent(s1, ef, 0);
    cudaStreamWaitEvent(s2, ef, 0);

    cudaStream_t streams[NCHUNK] = {0, s1, s2};
    for (int c = 0; c < NCHUNK; c++) {
        cudaStream_t st = streams[c];
        int bt0 = c * CH;
        k_qkv <<<CH*16,   256, 0,       st>>>(x, eigvec, eigval, Wq, bq, Wk, bk, Wv, bv, Wp, bt0);
        k_gat <<<CH*Nn/8, 256, 0,       st>>>(adj, bp, bt0);
        k_attn<<<CH,      1024, 145600, st>>>(Wo, bo, bt0);
        k_out <<<CH*16,   256, 17408,   st>>>(W1, b1, W2, b2, out, bt0);
    }

    // join
    cudaEventRecord(e1, s1);
    cudaEventRecord(e2, s2);
    cudaStreamWaitEvent(0, e1, 0);
    cudaStreamWaitEvent(0, e2, 0);
}

// round 16
// speedup vs baseline: 1.0577x; 1.0577x over previous
#include <cuda_runtime.h>

#define BT 96
#define CH 32              // bt per chunk (R8-proven optimum)
#define NCHUNK 3
#define Nn 512
#define Dd 64
#define NNb 16
#define MS 45

// ---------------- device scratch ----------------
__device__ float g_xq[BT*Nn*Dd];
__device__ float g_Q [BT*Nn*Dd];
__device__ float g_K [BT*Nn*Dd];
__device__ float g_V [BT*Nn*Dd];
__device__ float g_u [BT*Nn];
__device__ float g_M [BT*Nn];
__device__ float g_avo[BT*48*Dd];
__device__ int   g_cp[BT*Nn];

// ---------------- packed f32x2 helpers ----------------
__device__ __forceinline__ unsigned long long pk2(float lo, float hi) {
    unsigned long long r;
    asm("mov.b64 %0, {%1, %2};" : "=l"(r) : "f"(lo), "f"(hi));
    return r;
}
__device__ __forceinline__ void fma2(unsigned long long& a, unsigned long long x,
                                     unsigned long long w) {
    asm("fma.rn.f32x2 %0, %1, %2, %0;" : "+l"(a) : "l"(x), "l"(w));
}
__device__ __forceinline__ float2 up2(unsigned long long v) {
    float lo, hi;
    asm("mov.b64 {%0, %1}, %2;" : "=f"(lo), "=f"(hi) : "l"(v));
    float2 r; r.x = lo; r.y = hi; return r;
}

// ---------------- K1: x_ = x + ev ; Q,K,V GEMMs + u = V.Wp ----------------
// 256 threads, 32 rows/CTA, thread tile 2 rows x 4 cols
__global__ void __launch_bounds__(256) k_qkv(
    const float* __restrict__ x, const float* __restrict__ eigvec,
    const float* __restrict__ eigval,
    const float* __restrict__ Wq, const float* __restrict__ bq,
    const float* __restrict__ Wk, const float* __restrict__ bk,
    const float* __restrict__ Wv, const float* __restrict__ bv,
    const float* __restrict__ Wp, int bt0)
{
    __shared__ __align__(16) float xs[32*64];
    int bt = bt0 + (blockIdx.x >> 4);
    int nb = (blockIdx.x & 15) * 32;
    int tid = threadIdx.x;

    for (int idx = tid; idx < 2048; idx += 256) {
        int r = idx >> 6, d = idx & 63;
        int n = nb + r;
        float v = x[(bt*Nn + n)*Dd + d] + eigvec[d*Nn + n] * eigval[d];
        xs[idx] = v;
        g_xq[(bt*Nn + n)*Dd + d] = v;
    }
    __syncthreads();

    int rg = tid >> 4, j4 = tid & 15;
    const float4* wq4 = (const float4*)Wq;
    const float4* wk4 = (const float4*)Wk;
    const float4* wv4 = (const float4*)Wv;

    unsigned long long q01[2], q23[2], k01[2], k23[2], v01[2], v23[2];
    {
        float4 b = __ldg((const float4*)bq + j4);
        #pragma unroll
        for (int i = 0; i < 2; i++) { q01[i] = pk2(b.x, b.y); q23[i] = pk2(b.z, b.w); }
        b = __ldg((const float4*)bk + j4);
        #pragma unroll
        for (int i = 0; i < 2; i++) { k01[i] = pk2(b.x, b.y); k23[i] = pk2(b.z, b.w); }
        b = __ldg((const float4*)bv + j4);
        #pragma unroll
        for (int i = 0; i < 2; i++) { v01[i] = pk2(b.x, b.y); v23[i] = pk2(b.z, b.w); }
    }

    const float4* xp = (const float4*)xs;
    #pragma unroll
    for (int d4 = 0; d4 < 16; d4++) {
        float4 xr[2];
        xr[0] = xp[(rg*2+0)*16 + d4];
        xr[1] = xp[(rg*2+1)*16 + d4];
        #pragma unroll
        for (int kk = 0; kk < 4; kk++) {
            float4 wq = __ldg(wq4 + (d4*4+kk)*16 + j4);
            float4 wk = __ldg(wk4 + (d4*4+kk)*16 + j4);
            float4 wv = __ldg(wv4 + (d4*4+kk)*16 + j4);
            unsigned long long wq01 = pk2(wq.x, wq.y), wq23 = pk2(wq.z, wq.w);
            unsigned long long wk01 = pk2(wk.x, wk.y), wk23 = pk2(wk.z, wk.w);
            unsigned long long wv01 = pk2(wv.x, wv.y), wv23 = pk2(wv.z, wv.w);
            #pragma unroll
            for (int i = 0; i < 2; i++) {
                float xv = ((const float*)&xr[i])[kk];
                unsigned long long x2 = pk2(xv, xv);
                fma2(q01[i], x2, wq01); fma2(q23[i], x2, wq23);
                fma2(k01[i], x2, wk01); fma2(k23[i], x2, wk23);
                fma2(v01[i], x2, wv01); fma2(v23[i], x2, wv23);
            }
        }
    }

    float4 wp = __ldg((const float4*)Wp + j4);
    int nbase = (bt*Nn + nb + rg*2)*Dd;
    float up[2];
    #pragma unroll
    for (int i = 0; i < 2; i++) {
        float2 a = up2(q01[i]), b = up2(q23[i]);
        float4 o; o.x=a.x; o.y=a.y; o.z=b.x; o.w=b.y;
        ((float4*)(g_Q + nbase + i*Dd))[j4] = o;
        a = up2(k01[i]); b = up2(k23[i]);
        o.x=a.x; o.y=a.y; o.z=b.x; o.w=b.y;
        ((float4*)(g_K + nbase + i*Dd))[j4] = o;
        a = up2(v01[i]); b = up2(v23[i]);
        o.x=a.x; o.y=a.y; o.z=b.x; o.w=b.y;
        ((float4*)(g_V + nbase + i*Dd))[j4] = o;
        up[i] = o.x*wp.x + o.y*wp.y + o.z*wp.z + o.w*wp.w;
    }
    #pragma unroll
    for (int o = 8; o; o >>= 1) {
        #pragma unroll
        for (int i = 0; i < 2; i++)
            up[i] += __shfl_xor_sync(0xffffffffu, up[i], o);
    }
    if (j4 == 0) {
        g_u[bt*Nn + nb + rg*2    ] = up[0];
        g_u[bt*Nn + nb + rg*2 + 1] = up[1];
    }
}

// ---------------- K2: M[n] = Q[n] . sum_k u[j]K[j] + bp ----------------
// 2 nodes per warp: 16 lanes x float4 cover one 64-float row
__global__ void k_gat(const int* __restrict__ adj, const float* __restrict__ bp,
                      int bt0)
{
    int warp = threadIdx.x >> 5, lane = threadIdx.x & 31;
    int g16 = lane >> 4, l = lane & 15;       // node-subgroup, lane-in-group
    int lg = (blockIdx.x * 8 + warp) * 2 + g16;   // local node index in chunk
    int bt = bt0 + (lg >> 9), n = lg & 511;
    int base = bt*Nn*Dd;

    float4 acc = make_float4(0.f, 0.f, 0.f, 0.f);
    #pragma unroll
    for (int k = 0; k < NNb; k++) {
        int j = __ldg(adj + n*NNb + k);
        float uj = __ldg(g_u + bt*Nn + j);
        float4 kk = ((const float4*)(g_K + base + j*Dd))[l];
        acc.x += uj*kk.x; acc.y += uj*kk.y; acc.z += uj*kk.z; acc.w += uj*kk.w;
    }
    float4 q = ((const float4*)(g_Q + base + n*Dd))[l];
    float mm = q.x*acc.x + q.y*acc.y + q.z*acc.z + q.w*acc.w;
    #pragma unroll
    for (int o = 8; o; o >>= 1) mm += __shfl_xor_sync(0xffffffffu, mm, o);
    if (l == 0) g_M[bt*Nn + n] = mm + __ldg(bp);
}

// ---------------- K3: topk + scores + softmax + cp + AV + avo ----------------
// dyn smem floats: sc[48*512] qs[48*64] ts[128*68] + ti[48] ints
__global__ void __launch_bounds__(1024) k_attn(const float* __restrict__ Wo,
                                               const float* __restrict__ bo,
                                               int bt0)
{
    extern __shared__ __align__(16) float sm[];
    float* sc = sm;                       // 24576
    float* qs = sm + 24576;               // 3072
    float* ts = qs + 3072;                // 8704 (128 rows, stride 68)
    int*   ti = (int*)(ts + 8704);        // 48

    int bt = bt0 + blockIdx.x, tid = threadIdx.x;   // 1024 threads
    int base = bt*Nn*Dd;

    // ---- preload K tile 0 into ts (latency hidden behind the sort) ----
    for (int idx = tid; idx < 2048; idx += 1024) {
        int r = idx >> 4, d4 = idx & 15;
        ((float4*)ts)[r*17 + d4] = ((const float4*)(g_K + base))[r*16 + d4];
    }

    // ---- top-45 hybrid bitonic (register keys; shfl j<32, smem j>=32) ----
    {
        unsigned long long* skey = (unsigned long long*)sc;
        unsigned long long key = 0;
        if (tid < 512) {
            float f = g_M[bt*Nn + tid];
            unsigned int u = __float_as_uint(f);
            u = (u & 0x80000000u) ? ~u : (u | 0x80000000u);
            key = ((unsigned long long)u << 32) | (unsigned)tid;
        }
        for (int k = 2; k <= 512; k <<= 1) {
            for (int j = k >> 1; j > 0; j >>= 1) {
                if (j >= 32) {
                    if (tid < 512) skey[tid] = key;
                    __syncthreads();
                    if (tid < 512) {
                        unsigned long long partner = skey[tid ^ j];
                        bool up = ((tid & k) == 0);
                        bool lower = ((tid & j) == 0);
                        unsigned long long mn = key < partner ? key : partner;
                        unsigned long long mx = key < partner ? partner : key;
                        key = (up == lower) ? mn : mx;
                    }
                    __syncthreads();
                } else {
                    if (tid < 512) {
                        unsigned long long partner =
                            __shfl_xor_sync(0xffffffffu, key, j);
                        bool up = ((tid & k) == 0);
                        bool lower = ((tid & j) == 0);
                        unsigned long long mn = key < partner ? key : partner;
                        unsigned long long mx = key < partner ? partner : key;
                        key = (up == lower) ? mn : mx;
                    }
                }
            }
        }
        if (tid >= 512 - MS && tid < 512)
            ti[511 - tid] = (int)(key & 0xffffffffu);
        __syncthreads();
    }

    // ---- gather Q_red (48 rows; 45..47 zero) ----
    for (int idx = tid; idx < 48*64; idx += 1024) {
        int m = idx >> 6, d = idx & 63;
        qs[idx] = (m < MS) ? g_Q[base + ti[m]*Dd + d] : 0.f;
    }

    const float4* qs4 = (const float4*)qs;
    int mi = tid >> 6, ri = tid & 63;

    // ---- scores: 4 tiles of 128 K-rows (tile 0 already resident) ----
    for (int t = 0; t < 4; t++) {
        __syncthreads();
        if (t > 0) {
            for (int idx = tid; idx < 2048; idx += 1024) {
                int r = idx >> 4, d4 = idx & 15;
                ((float4*)ts)[r*17 + d4] = ((const float4*)(g_K + base))[(t*128 + r)*16 + d4];
            }
            __syncthreads();
        }
        float s00=0,s01=0,s10=0,s11=0,s20=0,s21=0;
        const float4* tk = (const float4*)ts;
        #pragma unroll
        for (int d4 = 0; d4 < 16; d4++) {
            float4 q0 = qs4[(mi     )*16 + d4];
            float4 q1 = qs4[(mi + 16)*16 + d4];
            float4 q2 = qs4[(mi + 32)*16 + d4];
            float4 k0 = tk[ri*17 + d4];
            float4 k1 = tk[(ri+64)*17 + d4];
            s00 += q0.x*k0.x + q0.y*k0.y + q0.z*k0.z + q0.w*k0.w;
            s01 += q0.x*k1.x + q0.y*k1.y + q0.z*k1.z + q0.w*k1.w;
            s10 += q1.x*k0.x + q1.y*k0.y + q1.z*k0.z + q1.w*k0.w;
            s11 += q1.x*k1.x + q1.y*k1.y + q1.z*k1.z + q1.w*k1.w;
            s20 += q2.x*k0.x + q2.y*k0.y + q2.z*k0.z + q2.w*k0.w;
            s21 += q2.x*k1.x + q2.y*k1.y + q2.z*k1.z + q2.w*k1.w;
        }
        int nb = t*128;
        sc[(mi     )*512 + nb + ri     ] = s00*0.125f;
        sc[(mi     )*512 + nb + ri + 64] = s01*0.125f;
        sc[(mi + 16)*512 + nb + ri     ] = s10*0.125f;
        sc[(mi + 16)*512 + nb + ri + 64] = s11*0.125f;
        sc[(mi + 32)*512 + nb + ri     ] = s20*0.125f;
        sc[(mi + 32)*512 + nb + ri + 64] = s21*0.125f;
    }
    __syncthreads();

    // ---- preload V tile 0 into ts (dead region during softmax/cp) ----
    for (int idx = tid; idx < 2048; idx += 1024) {
        int r = idx >> 4, d4 = idx & 15;
        ((float4*)ts)[r*17 + d4] = ((const float4*)(g_V + base))[r*16 + d4];
    }

    // ---- softmax (warp per row) ----
    {
        int warp = tid >> 5, lane = tid & 31;
        for (int m = warp; m < MS; m += 32) {
            float* row = sc + m*512;
            float rv[16];
            float mx = -1e30f;
            #pragma unroll
            for (int k = 0; k < 16; k++) { rv[k] = row[lane + 32*k]; mx = fmaxf(mx, rv[k]); }
            #pragma unroll
            for (int o = 16; o; o >>= 1) mx = fmaxf(mx, __shfl_xor_sync(0xffffffffu, mx, o));
            float s = 0.f;
            #pragma unroll
            for (int k = 0; k < 16; k++) { rv[k] = __expf(rv[k] - mx); s += rv[k]; }
            #pragma unroll
            for (int o = 16; o; o >>= 1) s += __shfl_xor_sync(0xffffffffu, s, o);
            float rinv = 1.f / s;
            #pragma unroll
            for (int k = 0; k < 16; k++) row[lane + 32*k] = rv[k]*rinv;
        }
        for (int idx = tid; idx < 3*512; idx += 1024) sc[MS*512 + idx] = 0.f;
    }
    __syncthreads();

    // ---- cp = argmax_m attn[:,n] (first-max ties) ----
    if (tid < 512) {
        int n = tid;
        float bv = sc[n]; int bi = 0;
        for (int m = 1; m < MS; m++) {
            float v = sc[m*512 + n];
            if (v > bv) { bv = v; bi = m; }
        }
        g_cp[bt*Nn + n] = bi;
    }

    // ---- av = attn @ V (tile 0 already resident) ----
    int di = ri;
    float a0 = 0.f, a1 = 0.f, a2 = 0.f;
    for (int t = 0; t < 4; t++) {
        __syncthreads();
        if (t > 0) {
            for (int idx = tid; idx < 2048; idx += 1024) {
                int r = idx >> 4, d4 = idx & 15;
                ((float4*)ts)[r*17 + d4] = ((const float4*)(g_V + base))[(t*128 + r)*16 + d4];
            }
            __syncthreads();
        }
        const float4* p0 = (const float4*)(sc + (mi     )*512 + t*128);
        const float4* p1 = (const float4*)(sc + (mi + 16)*512 + t*128);
        const float4* p2 = (const float4*)(sc + (mi + 32)*512 + t*128);
        #pragma unroll
        for (int r4 = 0; r4 < 32; r4++) {
            float4 w0 = p0[r4], w1 = p1[r4], w2 = p2[r4];
            float v;
            v = ts[(r4*4+0)*68 + di]; a0 += w0.x*v; a1 += w1.x*v; a2 += w2.x*v;
            v = ts[(r4*4+1)*68 + di]; a0 += w0.y*v; a1 += w1.y*v; a2 += w2.y*v;
            v = ts[(r4*4+2)*68 + di]; a0 += w0.z*v; a1 += w1.z*v; a2 += w2.z*v;
            v = ts[(r4*4+3)*68 + di]; a0 += w0.w*v; a1 += w1.w*v; a2 += w2.w*v;
        }
    }
    __syncthreads();
    qs[(mi     )*64 + di] = a0;
    qs[(mi + 16)*64 + di] = a1;
    qs[(mi + 32)*64 + di] = a2;
    __syncthreads();

    // ---- avo = av @ Wo + bo ----
    {
        float b = __ldg(bo + di);
        float c0 = b, c1 = b, c2 = b;
        #pragma unroll
        for (int d4 = 0; d4 < 16; d4++) {
            float4 q0 = qs4[(mi     )*16 + d4];
            float4 q1 = qs4[(mi + 16)*16 + d4];
            float4 q2 = qs4[(mi + 32)*16 + d4];
            float w0 = __ldg(Wo + (d4*4+0)*64 + di);
            float w1 = __ldg(Wo + (d4*4+1)*64 + di);
            float w2 = __ldg(Wo + (d4*4+2)*64 + di);
            float w3 = __ldg(Wo + (d4*4+3)*64 + di);
            c0 += q0.x*w0 + q0.y*w1 + q0.z*w2 + q0.w*w3;
            c1 += q1.x*w0 + q1.y*w1 + q1.z*w2 + q1.w*w3;
            c2 += q2.x*w0 + q2.y*w1 + q2.z*w2 + q2.w*w3;
        }
        g_avo[(bt*48 + mi     )*64 + di] = c0;
        g_avo[(bt*48 + mi + 16)*64 + di] = c1;
        g_avo[(bt*48 + mi + 32)*64 + di] = c2;
    }
}

// ---------------- K4: gather + LN + FFN + LN -> out (R13 64-row version) ----
__global__ void __launch_bounds__(256) k_out(
    const float* __restrict__ W1, const float* __restrict__ b1,
    const float* __restrict__ W2, const float* __restrict__ b2,
    float* __restrict__ out, int bt0)
{
    extern __shared__ __align__(16) float sm[];
    float* vs = sm;          // 64 rows, stride 68
    float* hs = sm + 4352;

    int tid = threadIdx.x;   // 256
    int bt = bt0 + (blockIdx.x >> 3);
    int n0 = (blockIdx.x & 7) * 64;

    // gather avo[cp] + residual
    for (int idx = tid; idx < 1024; idx += 256) {
        int r = idx >> 4, d4 = idx & 15;
        int c = g_cp[bt*Nn + n0 + r];
        float4 a = ((const float4*)(g_avo + (bt*48 + c)*Dd))[d4];
        float4 b = ((const float4*)(g_xq + (bt*Nn + n0 + r)*Dd))[d4];
        a.x += b.x; a.y += b.y; a.z += b.z; a.w += b.w;
        ((float4*)vs)[r*17 + d4] = a;
    }
    __syncthreads();

    // LN rows of vs
    {
        int warp = tid >> 5, lane = tid & 31;
        for (int r = warp; r < 64; r += 8) {
            float a = vs[r*68 + lane], b = vs[r*68 + lane + 32];
            float s = a + b;
            #pragma unroll
            for (int o = 16; o; o >>= 1) s += __shfl_xor_sync(0xffffffffu, s, o);
            float mu = s * (1.f/64.f);
            float da = a - mu, db = b - mu;
            float v2 = da*da + db*db;
            #pragma unroll
            for (int o = 16; o; o >>= 1) v2 += __shfl_xor_sync(0xffffffffu, v2, o);
            float rr = rsqrtf(v2*(1.f/64.f) + 1e-5f);
            vs[r*68 + lane] = da*rr; vs[r*68 + lane + 32] = db*rr;
        }
    }
    __syncthreads();

    int rg = tid >> 4, j4 = tid & 15;
    const float4* w14 = (const float4*)W1;
    const float4* w24 = (const float4*)W2;
    float4 acc[4];

    // GEMM: hs = relu(vs@W1 + b1)
    {
        float4 b4 = __ldg((const float4*)b1 + j4);
        #pragma unroll
        for (int i = 0; i < 4; i++) acc[i] = b4;
        const float4* xp = (const float4*)vs;
        #pragma unroll
        for (int d4 = 0; d4 < 16; d4++) {
            float4 xr[4];
            #pragma unroll
            for (int i = 0; i < 4; i++) xr[i] = xp[(rg*4+i)*17 + d4];
            #pragma unroll
            for (int kk = 0; kk < 4; kk++) {
                float4 w = __ldg(w14 + (d4*4+kk)*16 + j4);
                #pragma unroll
                for (int i = 0; i < 4; i++) {
                    float xv = ((const float*)&xr[i])[kk];
                    acc[i].x += xv*w.x; acc[i].y += xv*w.y; acc[i].z += xv*w.z; acc[i].w += xv*w.w;
                }
            }
        }
        #pragma unroll
        for (int i = 0; i < 4; i++) {
            acc[i].x = fmaxf(acc[i].x, 0.f); acc[i].y = fmaxf(acc[i].y, 0.f);
            acc[i].z = fmaxf(acc[i].z, 0.f); acc[i].w = fmaxf(acc[i].w, 0.f);
            ((float4*)hs)[(rg*4+i)*17 + j4] = acc[i];
        }
    }
    __syncthreads();

    // GEMM: o = hs@W2 + b2 + vs -> vs
    {
        float4 b4 = __ldg((const float4*)b2 + j4);
        #pragma unroll
        for (int i = 0; i < 4; i++) acc[i] = b4;
        const float4* xp = (const float4*)hs;
        #pragma unroll
        for (int d4 = 0; d4 < 16; d4++) {
            float4 xr[4];
            #pragma unroll
            for (int i = 0; i < 4; i++) xr[i] = xp[(rg*4+i)*17 + d4];
            #pragma unroll
            for (int kk = 0; kk < 4; kk++) {
                float4 w = __ldg(w24 + (d4*4+kk)*16 + j4);
                #pragma unroll
                for (int i = 0; i < 4; i++) {
                    float xv = ((const float*)&xr[i])[kk];
                    acc[i].x += xv*w.x; acc[i].y += xv*w.y; acc[i].z += xv*w.z; acc[i].w += xv*w.w;
                }
            }
        }
        #pragma unroll
        for (int i = 0; i < 4; i++) {
            float4 vv = ((const float4*)vs)[(rg*4+i)*17 + j4];
            acc[i].x += vv.x; acc[i].y += vv.y; acc[i].z += vv.z; acc[i].w += vv.w;
        }
        __syncthreads();
        #pragma unroll
        for (int i = 0; i < 4; i++)
            ((float4*)vs)[(rg*4+i)*17 + j4] = acc[i];
    }
    __syncthreads();

    // final LN -> out
    {
        int warp = tid >> 5, lane = tid & 31;
        for (int r = warp; r < 64; r += 8) {
            float a = vs[r*68 + lane], b = vs[r*68 + lane + 32];
            float s = a + b;
            #pragma unroll
            for (int o = 16; o; o >>= 1) s += __shfl_xor_sync(0xffffffffu, s, o);
            float mu = s * (1.f/64.f);
            float da = a - mu, db = b - mu;
            float v2 = da*da + db*db;
            #pragma unroll
            for (int o = 16; o; o >>= 1) v2 += __shfl_xor_sync(0xffffffffu, v2, o);
            float rr = rsqrtf(v2*(1.f/64.f) + 1e-5f);
            float* po = out + (bt*Nn + n0 + r)*Dd;
            po[lane] = da*rr; po[lane + 32] = db*rr;
        }
    }
}

// ---------------- launch: 3-chunk pipelined streams (R8 config) -------------
extern "C" void kernel_launch(void* const* d_in, const int* in_sizes, int n_in,
                              void* d_out, int out_size)
{
    const float* x      = (const float*)d_in[0];
    const int*   adj    = (const int*)  d_in[1];
    const float* eigvec = (const float*)d_in[2];
    const float* eigval = (const float*)d_in[3];
    const float* Wq = (const float*)d_in[4];  const float* bq = (const float*)d_in[5];
    const float* Wk = (const float*)d_in[6];  const float* bk = (const float*)d_in[7];
    const float* Wv = (const float*)d_in[8];  const float* bv = (const float*)d_in[9];
    const float* Wo = (const float*)d_in[10]; const float* bo = (const float*)d_in[11];
    const float* Wp = (const float*)d_in[12]; const float* bp = (const float*)d_in[13];
    const float* W1 = (const float*)d_in[14]; const float* b1 = (const float*)d_in[15];
    const float* W2 = (const float*)d_in[16]; const float* b2 = (const float*)d_in[17];
    float* out = (float*)d_out;

    static cudaStream_t s1 = 0, s2 = 0;
    static cudaEvent_t ef = 0, e1 = 0, e2 = 0;
    static int inited = 0;
    if (!inited) {
        cudaStreamCreateWithFlags(&s1, cudaStreamNonBlocking);
        cudaStreamCreateWithFlags(&s2, cudaStreamNonBlocking);
        cudaEventCreateWithFlags(&ef, cudaEventDisableTiming);
        cudaEventCreateWithFlags(&e1, cudaEventDisableTiming);
        cudaEventCreateWithFlags(&e2, cudaEventDisableTiming);
        cudaFuncSetAttribute(k_attn, cudaFuncAttributeMaxDynamicSharedMemorySize, 145600);
        cudaFuncSetAttribute(k_out,  cudaFuncAttributeMaxDynamicSharedMemorySize, 34816);
        inited = 1;
    }

    // fork
    cudaEventRecord(ef, 0);
    cudaStreamWaitEvent(s1, ef, 0);
    cudaStreamWaitEvent(s2, ef, 0);

    cudaStream_t streams[NCHUNK] = {0, s1, s2};
    for (int c = 0; c < NCHUNK; c++) {
        cudaStream_t st = streams[c];
        int bt0 = c * CH;
        k_qkv <<<CH*16,    256, 0,       st>>>(x, eigvec, eigval, Wq, bq, Wk, bk, Wv, bv, Wp, bt0);
        k_gat <<<CH*Nn/16, 256, 0,       st>>>(adj, bp, bt0);
        k_attn<<<CH,       1024, 145600, st>>>(Wo, bo, bt0);
        k_out <<<CH*8,     256, 34816,   st>>>(W1, b1, W2, b2, out, bt0);
    }

    // join
    cudaEventRecord(e1, s1);
    cudaEventRecord(e2, s2);
    cudaStreamWaitEvent(0, e1, 0);
    cudaStreamWaitEvent(0, e2, 0);
}

// round 17
// speedup vs baseline: 1.0697x; 1.0114x over previous
#include <cuda_runtime.h>

#define BT 96
#define CH 32              // bt per chunk (R8-proven optimum)
#define NCHUNK 3
#define Nn 512
#define Dd 64
#define NNb 16
#define MS 45

// ---------------- device scratch ----------------
__device__ float g_xq[BT*Nn*Dd];
__device__ float g_Q [BT*Nn*Dd];
__device__ float g_K [BT*Nn*Dd];
__device__ float g_V [BT*Nn*Dd];
__device__ float g_u [BT*Nn];
__device__ float g_M [BT*Nn];
__device__ float g_avo[BT*48*Dd];
__device__ int   g_cp[BT*Nn];

// ---------------- packed f32x2 helpers ----------------
__device__ __forceinline__ unsigned long long pk2(float lo, float hi) {
    unsigned long long r;
    asm("mov.b64 %0, {%1, %2};" : "=l"(r) : "f"(lo), "f"(hi));
    return r;
}
__device__ __forceinline__ void fma2(unsigned long long& a, unsigned long long x,
                                     unsigned long long w) {
    asm("fma.rn.f32x2 %0, %1, %2, %0;" : "+l"(a) : "l"(x), "l"(w));
}
__device__ __forceinline__ float2 up2(unsigned long long v) {
    float lo, hi;
    asm("mov.b64 {%0, %1}, %2;" : "=f"(lo), "=f"(hi) : "l"(v));
    float2 r; r.x = lo; r.y = hi; return r;
}

// ---------------- K1: x_ = x + ev ; Q,K,V GEMMs + u = V.Wp ----------------
// 256 threads, 32 rows/CTA, thread tile 2 rows x 4 cols
__global__ void __launch_bounds__(256) k_qkv(
    const float* __restrict__ x, const float* __restrict__ eigvec,
    const float* __restrict__ eigval,
    const float* __restrict__ Wq, const float* __restrict__ bq,
    const float* __restrict__ Wk, const float* __restrict__ bk,
    const float* __restrict__ Wv, const float* __restrict__ bv,
    const float* __restrict__ Wp, int bt0)
{
    __shared__ __align__(16) float xs[32*64];
    int bt = bt0 + (blockIdx.x >> 4);
    int nb = (blockIdx.x & 15) * 32;
    int tid = threadIdx.x;

    for (int idx = tid; idx < 2048; idx += 256) {
        int r = idx >> 6, d = idx & 63;
        int n = nb + r;
        float v = x[(bt*Nn + n)*Dd + d] + eigvec[d*Nn + n] * eigval[d];
        xs[idx] = v;
        g_xq[(bt*Nn + n)*Dd + d] = v;
    }
    __syncthreads();

    int rg = tid >> 4, j4 = tid & 15;
    const float4* wq4 = (const float4*)Wq;
    const float4* wk4 = (const float4*)Wk;
    const float4* wv4 = (const float4*)Wv;

    unsigned long long q01[2], q23[2], k01[2], k23[2], v01[2], v23[2];
    {
        float4 b = __ldg((const float4*)bq + j4);
        #pragma unroll
        for (int i = 0; i < 2; i++) { q01[i] = pk2(b.x, b.y); q23[i] = pk2(b.z, b.w); }
        b = __ldg((const float4*)bk + j4);
        #pragma unroll
        for (int i = 0; i < 2; i++) { k01[i] = pk2(b.x, b.y); k23[i] = pk2(b.z, b.w); }
        b = __ldg((const float4*)bv + j4);
        #pragma unroll
        for (int i = 0; i < 2; i++) { v01[i] = pk2(b.x, b.y); v23[i] = pk2(b.z, b.w); }
    }

    const float4* xp = (const float4*)xs;
    #pragma unroll
    for (int d4 = 0; d4 < 16; d4++) {
        float4 xr[2];
        xr[0] = xp[(rg*2+0)*16 + d4];
        xr[1] = xp[(rg*2+1)*16 + d4];
        #pragma unroll
        for (int kk = 0; kk < 4; kk++) {
            float4 wq = __ldg(wq4 + (d4*4+kk)*16 + j4);
            float4 wk = __ldg(wk4 + (d4*4+kk)*16 + j4);
            float4 wv = __ldg(wv4 + (d4*4+kk)*16 + j4);
            unsigned long long wq01 = pk2(wq.x, wq.y), wq23 = pk2(wq.z, wq.w);
            unsigned long long wk01 = pk2(wk.x, wk.y), wk23 = pk2(wk.z, wk.w);
            unsigned long long wv01 = pk2(wv.x, wv.y), wv23 = pk2(wv.z, wv.w);
            #pragma unroll
            for (int i = 0; i < 2; i++) {
                float xv = ((const float*)&xr[i])[kk];
                unsigned long long x2 = pk2(xv, xv);
                fma2(q01[i], x2, wq01); fma2(q23[i], x2, wq23);
                fma2(k01[i], x2, wk01); fma2(k23[i], x2, wk23);
                fma2(v01[i], x2, wv01); fma2(v23[i], x2, wv23);
            }
        }
    }

    float4 wp = __ldg((const float4*)Wp + j4);
    int nbase = (bt*Nn + nb + rg*2)*Dd;
    float up[2];
    #pragma unroll
    for (int i = 0; i < 2; i++) {
        float2 a = up2(q01[i]), b = up2(q23[i]);
        float4 o; o.x=a.x; o.y=a.y; o.z=b.x; o.w=b.y;
        ((float4*)(g_Q + nbase + i*Dd))[j4] = o;
        a = up2(k01[i]); b = up2(k23[i]);
        o.x=a.x; o.y=a.y; o.z=b.x; o.w=b.y;
        ((float4*)(g_K + nbase + i*Dd))[j4] = o;
        a = up2(v01[i]); b = up2(v23[i]);
        o.x=a.x; o.y=a.y; o.z=b.x; o.w=b.y;
        ((float4*)(g_V + nbase + i*Dd))[j4] = o;
        up[i] = o.x*wp.x + o.y*wp.y + o.z*wp.z + o.w*wp.w;
    }
    #pragma unroll
    for (int o = 8; o; o >>= 1) {
        #pragma unroll
        for (int i = 0; i < 2; i++)
            up[i] += __shfl_xor_sync(0xffffffffu, up[i], o);
    }
    if (j4 == 0) {
        g_u[bt*Nn + nb + rg*2    ] = up[0];
        g_u[bt*Nn + nb + rg*2 + 1] = up[1];
    }
}

// ---------------- K2: M[n] = Q[n] . sum_k u[j]K[j] + bp ----------------
// 2 nodes per warp: 16 lanes x float4 cover one 64-float row
__global__ void k_gat(const int* __restrict__ adj, const float* __restrict__ bp,
                      int bt0)
{
    int warp = threadIdx.x >> 5, lane = threadIdx.x & 31;
    int g16 = lane >> 4, l = lane & 15;
    int lg = (blockIdx.x * 8 + warp) * 2 + g16;
    int bt = bt0 + (lg >> 9), n = lg & 511;
    int base = bt*Nn*Dd;

    float4 acc = make_float4(0.f, 0.f, 0.f, 0.f);
    #pragma unroll
    for (int k = 0; k < NNb; k++) {
        int j = __ldg(adj + n*NNb + k);
        float uj = __ldg(g_u + bt*Nn + j);
        float4 kk = ((const float4*)(g_K + base + j*Dd))[l];
        acc.x += uj*kk.x; acc.y += uj*kk.y; acc.z += uj*kk.z; acc.w += uj*kk.w;
    }
    float4 q = ((const float4*)(g_Q + base + n*Dd))[l];
    float mm = q.x*acc.x + q.y*acc.y + q.z*acc.z + q.w*acc.w;
    #pragma unroll
    for (int o = 8; o; o >>= 1) mm += __shfl_xor_sync(0xffffffffu, mm, o);
    if (l == 0) g_M[bt*Nn + n] = mm + __ldg(bp);
}

// ---------------- K3: topk + scores + softmax + cp + AV + avo ----------------
// dyn smem floats: sc[48*512] qs[48*64] ts[128*68] + ti[48] ints
__global__ void __launch_bounds__(1024) k_attn(const float* __restrict__ Wo,
                                               const float* __restrict__ bo,
                                               int bt0)
{
    extern __shared__ __align__(16) float sm[];
    float* sc = sm;                       // 24576
    float* qs = sm + 24576;               // 3072
    float* ts = qs + 3072;                // 8704 (128 rows, stride 68)
    int*   ti = (int*)(ts + 8704);        // 48

    int bt = bt0 + blockIdx.x, tid = threadIdx.x;   // 1024 threads
    int base = bt*Nn*Dd;

    // ---- preload K tile 0 into ts (latency hidden behind the sort) ----
    for (int idx = tid; idx < 2048; idx += 1024) {
        int r = idx >> 4, d4 = idx & 15;
        ((float4*)ts)[r*17 + d4] = ((const float4*)(g_K + base))[r*16 + d4];
    }

    // ---- top-45 hybrid bitonic (register keys; shfl j<32, smem j>=32) ----
    {
        unsigned long long* skey = (unsigned long long*)sc;
        unsigned long long key = 0;
        if (tid < 512) {
            float f = g_M[bt*Nn + tid];
            unsigned int u = __float_as_uint(f);
            u = (u & 0x80000000u) ? ~u : (u | 0x80000000u);
            key = ((unsigned long long)u << 32) | (unsigned)tid;
        }
        for (int k = 2; k <= 512; k <<= 1) {
            for (int j = k >> 1; j > 0; j >>= 1) {
                if (j >= 32) {
                    if (tid < 512) skey[tid] = key;
                    __syncthreads();
                    if (tid < 512) {
                        unsigned long long partner = skey[tid ^ j];
                        bool up = ((tid & k) == 0);
                        bool lower = ((tid & j) == 0);
                        unsigned long long mn = key < partner ? key : partner;
                        unsigned long long mx = key < partner ? partner : key;
                        key = (up == lower) ? mn : mx;
                    }
                    __syncthreads();
                } else {
                    if (tid < 512) {
                        unsigned long long partner =
                            __shfl_xor_sync(0xffffffffu, key, j);
                        bool up = ((tid & k) == 0);
                        bool lower = ((tid & j) == 0);
                        unsigned long long mn = key < partner ? key : partner;
                        unsigned long long mx = key < partner ? partner : key;
                        key = (up == lower) ? mn : mx;
                    }
                }
            }
        }
        if (tid >= 512 - MS && tid < 512)
            ti[511 - tid] = (int)(key & 0xffffffffu);
        __syncthreads();
    }

    // ---- gather Q_red (48 rows; 45..47 zero) ----
    for (int idx = tid; idx < 48*64; idx += 1024) {
        int m = idx >> 6, d = idx & 63;
        qs[idx] = (m < MS) ? g_Q[base + ti[m]*Dd + d] : 0.f;
    }

    const ulonglong2* qsl = (const ulonglong2*)qs;
    int mi = tid >> 6, ri = tid & 63;

    // ---- scores: 4 tiles of 128 K-rows (FFMA2; lo=even d, hi=odd d) ----
    for (int t = 0; t < 4; t++) {
        __syncthreads();
        if (t > 0) {
            for (int idx = tid; idx < 2048; idx += 1024) {
                int r = idx >> 4, d4 = idx & 15;
                ((float4*)ts)[r*17 + d4] = ((const float4*)(g_K + base))[(t*128 + r)*16 + d4];
            }
            __syncthreads();
        }
        unsigned long long s00=0,s01=0,s10=0,s11=0,s20=0,s21=0;
        const ulonglong2* tk = (const ulonglong2*)ts;
        #pragma unroll
        for (int d4 = 0; d4 < 16; d4++) {
            ulonglong2 q0 = qsl[(mi     )*16 + d4];
            ulonglong2 q1 = qsl[(mi + 16)*16 + d4];
            ulonglong2 q2 = qsl[(mi + 32)*16 + d4];
            ulonglong2 k0 = tk[ri*17 + d4];
            ulonglong2 k1 = tk[(ri+64)*17 + d4];
            fma2(s00, q0.x, k0.x); fma2(s00, q0.y, k0.y);
            fma2(s01, q0.x, k1.x); fma2(s01, q0.y, k1.y);
            fma2(s10, q1.x, k0.x); fma2(s10, q1.y, k0.y);
            fma2(s11, q1.x, k1.x); fma2(s11, q1.y, k1.y);
            fma2(s20, q2.x, k0.x); fma2(s20, q2.y, k0.y);
            fma2(s21, q2.x, k1.x); fma2(s21, q2.y, k1.y);
        }
        int nb = t*128;
        float2 f;
        f = up2(s00); sc[(mi     )*512 + nb + ri     ] = (f.x + f.y)*0.125f;
        f = up2(s01); sc[(mi     )*512 + nb + ri + 64] = (f.x + f.y)*0.125f;
        f = up2(s10); sc[(mi + 16)*512 + nb + ri     ] = (f.x + f.y)*0.125f;
        f = up2(s11); sc[(mi + 16)*512 + nb + ri + 64] = (f.x + f.y)*0.125f;
        f = up2(s20); sc[(mi + 32)*512 + nb + ri     ] = (f.x + f.y)*0.125f;
        f = up2(s21); sc[(mi + 32)*512 + nb + ri + 64] = (f.x + f.y)*0.125f;
    }
    __syncthreads();

    // ---- preload V tile 0 into ts (dead region during softmax/cp) ----
    for (int idx = tid; idx < 2048; idx += 1024) {
        int r = idx >> 4, d4 = idx & 15;
        ((float4*)ts)[r*17 + d4] = ((const float4*)(g_V + base))[r*16 + d4];
    }

    // ---- softmax (warp per row) ----
    {
        int warp = tid >> 5, lane = tid & 31;
        for (int m = warp; m < MS; m += 32) {
            float* row = sc + m*512;
            float rv[16];
            float mx = -1e30f;
            #pragma unroll
            for (int k = 0; k < 16; k++) { rv[k] = row[lane + 32*k]; mx = fmaxf(mx, rv[k]); }
            #pragma unroll
            for (int o = 16; o; o >>= 1) mx = fmaxf(mx, __shfl_xor_sync(0xffffffffu, mx, o));
            float s = 0.f;
            #pragma unroll
            for (int k = 0; k < 16; k++) { rv[k] = __expf(rv[k] - mx); s += rv[k]; }
            #pragma unroll
            for (int o = 16; o; o >>= 1) s += __shfl_xor_sync(0xffffffffu, s, o);
            float rinv = 1.f / s;
            #pragma unroll
            for (int k = 0; k < 16; k++) row[lane + 32*k] = rv[k]*rinv;
        }
        for (int idx = tid; idx < 3*512; idx += 1024) sc[MS*512 + idx] = 0.f;
    }
    __syncthreads();

    // ---- cp = argmax_m attn[:,n] (first-max ties) ----
    if (tid < 512) {
        int n = tid;
        float bv = sc[n]; int bi = 0;
        for (int m = 1; m < MS; m++) {
            float v = sc[m*512 + n];
            if (v > bv) { bv = v; bi = m; }
        }
        g_cp[bt*Nn + n] = bi;
    }

    // ---- av = attn @ V (FFMA2; lo=even r, hi=odd r; tile 0 resident) ----
    int di = ri;
    unsigned long long A0 = 0, A1 = 0, A2 = 0;
    for (int t = 0; t < 4; t++) {
        __syncthreads();
        if (t > 0) {
            for (int idx = tid; idx < 2048; idx += 1024) {
                int r = idx >> 4, d4 = idx & 15;
                ((float4*)ts)[r*17 + d4] = ((const float4*)(g_V + base))[(t*128 + r)*16 + d4];
            }
            __syncthreads();
        }
        const ulonglong2* p0 = (const ulonglong2*)(sc + (mi     )*512 + t*128);
        const ulonglong2* p1 = (const ulonglong2*)(sc + (mi + 16)*512 + t*128);
        const ulonglong2* p2 = (const ulonglong2*)(sc + (mi + 32)*512 + t*128);
        #pragma unroll
        for (int r4 = 0; r4 < 32; r4++) {
            ulonglong2 w0 = p0[r4], w1 = p1[r4], w2 = p2[r4];
            float v0 = ts[(r4*4+0)*68 + di];
            float v1 = ts[(r4*4+1)*68 + di];
            float v2 = ts[(r4*4+2)*68 + di];
            float v3 = ts[(r4*4+3)*68 + di];
            unsigned long long v01 = pk2(v0, v1), v23 = pk2(v2, v3);
            fma2(A0, w0.x, v01); fma2(A0, w0.y, v23);
            fma2(A1, w1.x, v01); fma2(A1, w1.y, v23);
            fma2(A2, w2.x, v01); fma2(A2, w2.y, v23);
        }
    }
    __syncthreads();
    {
        float2 f;
        f = up2(A0); qs[(mi     )*64 + di] = f.x + f.y;
        f = up2(A1); qs[(mi + 16)*64 + di] = f.x + f.y;
        f = up2(A2); qs[(mi + 32)*64 + di] = f.x + f.y;
    }
    __syncthreads();

    // ---- avo = av @ Wo + bo (FFMA2; lo=even d, hi=odd d) ----
    {
        unsigned long long C0 = 0, C1 = 0, C2 = 0;
        #pragma unroll
        for (int d4 = 0; d4 < 16; d4++) {
            ulonglong2 q0 = qsl[(mi     )*16 + d4];
            ulonglong2 q1 = qsl[(mi + 16)*16 + d4];
            ulonglong2 q2 = qsl[(mi + 32)*16 + d4];
            float w0 = __ldg(Wo + (d4*4+0)*64 + di);
            float w1 = __ldg(Wo + (d4*4+1)*64 + di);
            float w2 = __ldg(Wo + (d4*4+2)*64 + di);
            float w3 = __ldg(Wo + (d4*4+3)*64 + di);
            unsigned long long w01 = pk2(w0, w1), w23 = pk2(w2, w3);
            fma2(C0, q0.x, w01); fma2(C0, q0.y, w23);
            fma2(C1, q1.x, w01); fma2(C1, q1.y, w23);
            fma2(C2, q2.x, w01); fma2(C2, q2.y, w23);
        }
        float b = __ldg(bo + di);
        float2 f;
        f = up2(C0); g_avo[(bt*48 + mi     )*64 + di] = b + f.x + f.y;
        f = up2(C1); g_avo[(bt*48 + mi + 16)*64 + di] = b + f.x + f.y;
        f = up2(C2); g_avo[(bt*48 + mi + 32)*64 + di] = b + f.x + f.y;
    }
}

// ---------------- K4: gather + LN + FFN + LN -> out (R13 64-row version) ----
__global__ void __launch_bounds__(256) k_out(
    const float* __restrict__ W1, const float* __restrict__ b1,
    const float* __restrict__ W2, const float* __restrict__ b2,
    float* __restrict__ out, int bt0)
{
    extern __shared__ __align__(16) float sm[];
    float* vs = sm;          // 64 rows, stride 68
    float* hs = sm + 4352;

    int tid = threadIdx.x;   // 256
    int bt = bt0 + (blockIdx.x >> 3);
    int n0 = (blockIdx.x & 7) * 64;

    // gather avo[cp] + residual
    for (int idx = tid; idx < 1024; idx += 256) {
        int r = idx >> 4, d4 = idx & 15;
        int c = g_cp[bt*Nn + n0 + r];
        float4 a = ((const float4*)(g_avo + (bt*48 + c)*Dd))[d4];
        float4 b = ((const float4*)(g_xq + (bt*Nn + n0 + r)*Dd))[d4];
        a.x += b.x; a.y += b.y; a.z += b.z; a.w += b.w;
        ((float4*)vs)[r*17 + d4] = a;
    }
    __syncthreads();

    // LN rows of vs
    {
        int warp = tid >> 5, lane = tid & 31;
        for (int r = warp; r < 64; r += 8) {
            float a = vs[r*68 + lane], b = vs[r*68 + lane + 32];
            float s = a + b;
            #pragma unroll
            for (int o = 16; o; o >>= 1) s += __shfl_xor_sync(0xffffffffu, s, o);
            float mu = s * (1.f/64.f);
            float da = a - mu, db = b - mu;
            float v2 = da*da + db*db;
            #pragma unroll
            for (int o = 16; o; o >>= 1) v2 += __shfl_xor_sync(0xffffffffu, v2, o);
            float rr = rsqrtf(v2*(1.f/64.f) + 1e-5f);
            vs[r*68 + lane] = da*rr; vs[r*68 + lane + 32] = db*rr;
        }
    }
    __syncthreads();

    int rg = tid >> 4, j4 = tid & 15;
    const float4* w14 = (const float4*)W1;
    const float4* w24 = (const float4*)W2;
    float4 acc[4];

    // GEMM: hs = relu(vs@W1 + b1)
    {
        float4 b4 = __ldg((const float4*)b1 + j4);
        #pragma unroll
        for (int i = 0; i < 4; i++) acc[i] = b4;
        const float4* xp = (const float4*)vs;
        #pragma unroll
        for (int d4 = 0; d4 < 16; d4++) {
            float4 xr[4];
            #pragma unroll
            for (int i = 0; i < 4; i++) xr[i] = xp[(rg*4+i)*17 + d4];
            #pragma unroll
            for (int kk = 0; kk < 4; kk++) {
                float4 w = __ldg(w14 + (d4*4+kk)*16 + j4);
                #pragma unroll
                for (int i = 0; i < 4; i++) {
                    float xv = ((const float*)&xr[i])[kk];
                    acc[i].x += xv*w.x; acc[i].y += xv*w.y; acc[i].z += xv*w.z; acc[i].w += xv*w.w;
                }
            }
        }
        #pragma unroll
        for (int i = 0; i < 4; i++) {
            acc[i].x = fmaxf(acc[i].x, 0.f); acc[i].y = fmaxf(acc[i].y, 0.f);
            acc[i].z = fmaxf(acc[i].z, 0.f); acc[i].w = fmaxf(acc[i].w, 0.f);
            ((float4*)hs)[(rg*4+i)*17 + j4] = acc[i];
        }
    }
    __syncthreads();

    // GEMM: o = hs@W2 + b2 + vs -> vs
    {
        float4 b4 = __ldg((const float4*)b2 + j4);
        #pragma unroll
        for (int i = 0; i < 4; i++) acc[i] = b4;
        const float4* xp = (const float4*)hs;
        #pragma unroll
        for (int d4 = 0; d4 < 16; d4++) {
            float4 xr[4];
            #pragma unroll
            for (int i = 0; i < 4; i++) xr[i] = xp[(rg*4+i)*17 + d4];
            #pragma unroll
            for (int kk = 0; kk < 4; kk++) {
                float4 w = __ldg(w24 + (d4*4+kk)*16 + j4);
                #pragma unroll
                for (int i = 0; i < 4; i++) {
                    float xv = ((const float*)&xr[i])[kk];
                    acc[i].x += xv*w.x; acc[i].y += xv*w.y; acc[i].z += xv*w.z; acc[i].w += xv*w.w;
                }
            }
        }
        #pragma unroll
        for (int i = 0; i < 4; i++) {
            float4 vv = ((const float4*)vs)[(rg*4+i)*17 + j4];
            acc[i].x += vv.x; acc[i].y += vv.y; acc[i].z += vv.z; acc[i].w += vv.w;
        }
        __syncthreads();
        #pragma unroll
        for (int i = 0; i < 4; i++)
            ((float4*)vs)[(rg*4+i)*17 + j4] = acc[i];
    }
    __syncthreads();

    // final LN -> out
    {
        int warp = tid >> 5, lane = tid & 31;
        for (int r = warp; r < 64; r += 8) {
            float a = vs[r*68 + lane], b = vs[r*68 + lane + 32];
            float s = a + b;
            #pragma unroll
            for (int o = 16; o; o >>= 1) s += __shfl_xor_sync(0xffffffffu, s, o);
            float mu = s * (1.f/64.f);
            float da = a - mu, db = b - mu;
            float v2 = da*da + db*db;
            #pragma unroll
            for (int o = 16; o; o >>= 1) v2 += __shfl_xor_sync(0xffffffffu, v2, o);
            float rr = rsqrtf(v2*(1.f/64.f) + 1e-5f);
            float* po = out + (bt*Nn + n0 + r)*Dd;
            po[lane] = da*rr; po[lane + 32] = db*rr;
        }
    }
}

// ---------------- launch: 3-chunk pipelined streams (R8 config) -------------
extern "C" void kernel_launch(void* const* d_in, const int* in_sizes, int n_in,
                              void* d_out, int out_size)
{
    const float* x      = (const float*)d_in[0];
    const int*   adj    = (const int*)  d_in[1];
    const float* eigvec = (const float*)d_in[2];
    const float* eigval = (const float*)d_in[3];
    const float* Wq = (const float*)d_in[4];  const float* bq = (const float*)d_in[5];
    const float* Wk = (const float*)d_in[6];  const float* bk = (const float*)d_in[7];
    const float* Wv = (const float*)d_in[8];  const float* bv = (const float*)d_in[9];
    const float* Wo = (const float*)d_in[10]; const float* bo = (const float*)d_in[11];
    const float* Wp = (const float*)d_in[12]; const float* bp = (const float*)d_in[13];
    const float* W1 = (const float*)d_in[14]; const float* b1 = (const float*)d_in[15];
    const float* W2 = (const float*)d_in[16]; const float* b2 = (const float*)d_in[17];
    float* out = (float*)d_out;

    static cudaStream_t s1 = 0, s2 = 0;
    static cudaEvent_t ef = 0, e1 = 0, e2 = 0;
    static int inited = 0;
    if (!inited) {
        cudaStreamCreateWithFlags(&s1, cudaStreamNonBlocking);
        cudaStreamCreateWithFlags(&s2, cudaStreamNonBlocking);
        cudaEventCreateWithFlags(&ef, cudaEventDisableTiming);
        cudaEventCreateWithFlags(&e1, cudaEventDisableTiming);
        cudaEventCreateWithFlags(&e2, cudaEventDisableTiming);
        cudaFuncSetAttribute(k_attn, cudaFuncAttributeMaxDynamicSharedMemorySize, 145600);
        cudaFuncSetAttribute(k_out,  cudaFuncAttributeMaxDynamicSharedMemorySize, 34816);
        inited = 1;
    }

    // fork
    cudaEventRecord(ef, 0);
    cudaStreamWaitEvent(s1, ef, 0);
    cudaStreamWaitEvent(s2, ef, 0);

    cudaStream_t streams[NCHUNK] = {0, s1, s2};
    for (int c = 0; c < NCHUNK; c++) {
        cudaStream_t st = streams[c];
        int bt0 = c * CH;
        k_qkv <<<CH*16,    256, 0,       st>>>(x, eigvec, eigval, Wq, bq, Wk, bk, Wv, bv, Wp, bt0);
        k_gat <<<CH*Nn/16, 256, 0,       st>>>(adj, bp, bt0);
        k_attn<<<CH,       1024, 145600, st>>>(Wo, bo, bt0);
        k_out <<<CH*8,     256, 34816,   st>>>(W1, b1, W2, b2, out, bt0);
    }

    // join
    cudaEventRecord(e1, s1);
    cudaEventRecord(e2, s2);
    cudaStreamWaitEvent(0, e1, 0);
    cudaStreamWaitEvent(0, e2, 0);
}